// round 2
// baseline (speedup 1.0000x reference)
#include <cuda_runtime.h>
#include <cuda_bf16.h>

#define Bv 8
#define Tv 512
#define Mv 16
#define Dv 128
#define Pv 256
#define Hv 8
#define Ev 32
#define ROWS (Bv*Tv*Mv)   // 65536

// Scratch for projected Q,K,V (layout identical to output: ((b*T+t)*M+m)*P + h*E + e)
__device__ float g_q[(size_t)ROWS * Pv];
__device__ float g_k[(size_t)ROWS * Pv];
__device__ float g_v[(size_t)ROWS * Pv];

// ---------------------------------------------------------------------------
// QKV projection: C[r][c] = sum_k A[r][k] * W[k][c] + bias[c]
// A: [65536 x 128], W: [128 x 256].  64x64 output tile, BK=64, 256 threads,
// 4x4 accumulators per thread.
// ---------------------------------------------------------------------------
__global__ __launch_bounds__(256) void qkv_gemm(
    const float* __restrict__ A, const float* __restrict__ W,
    const float* __restrict__ bias, int which)
{
    __shared__ float As[64][65];
    __shared__ float Bs[64][64];

    float* __restrict__ C = (which == 0) ? g_q : (which == 1) ? g_k : g_v;

    const int tid = threadIdx.x;
    const int tx  = tid & 15;         // 0..15
    const int ty  = tid >> 4;         // 0..15
    const int rowBase = blockIdx.x * 64;
    const int colBase = blockIdx.y * 64;

    float acc[4][4] = {};

    for (int kk = 0; kk < Dv; kk += 64) {
        #pragma unroll
        for (int i = tid; i < 64 * 64; i += 256) {
            int r = i >> 6, k = i & 63;
            As[r][k] = A[(size_t)(rowBase + r) * Dv + kk + k];
        }
        #pragma unroll
        for (int i = tid; i < 64 * 64; i += 256) {
            int k = i >> 6, c = i & 63;
            Bs[k][c] = W[(size_t)(kk + k) * Pv + colBase + c];
        }
        __syncthreads();

        #pragma unroll 16
        for (int k = 0; k < 64; k++) {
            float a0 = As[ty * 4 + 0][k];
            float a1 = As[ty * 4 + 1][k];
            float a2 = As[ty * 4 + 2][k];
            float a3 = As[ty * 4 + 3][k];
            float4 bb = *(const float4*)&Bs[k][tx * 4];
            acc[0][0] += a0 * bb.x; acc[0][1] += a0 * bb.y; acc[0][2] += a0 * bb.z; acc[0][3] += a0 * bb.w;
            acc[1][0] += a1 * bb.x; acc[1][1] += a1 * bb.y; acc[1][2] += a1 * bb.z; acc[1][3] += a1 * bb.w;
            acc[2][0] += a2 * bb.x; acc[2][1] += a2 * bb.y; acc[2][2] += a2 * bb.z; acc[2][3] += a2 * bb.w;
            acc[3][0] += a3 * bb.x; acc[3][1] += a3 * bb.y; acc[3][2] += a3 * bb.z; acc[3][3] += a3 * bb.w;
        }
        __syncthreads();
    }

    #pragma unroll
    for (int i = 0; i < 4; i++) {
        int r = rowBase + ty * 4 + i;
        float4 o;
        o.x = acc[i][0] + bias[colBase + tx * 4 + 0];
        o.y = acc[i][1] + bias[colBase + tx * 4 + 1];
        o.z = acc[i][2] + bias[colBase + tx * 4 + 2];
        o.w = acc[i][3] + bias[colBase + tx * 4 + 3];
        *(float4*)&C[(size_t)r * Pv + colBase + tx * 4] = o;
    }
}

// ---------------------------------------------------------------------------
// Attention: one block per (q-tile of 128, bmh). 128 threads, 1 thread = 1
// query row. K/V staged in smem 64 keys at a time. Online softmax with lazy
// rescale.  mask is int32 (bool promoted by harness).
// ---------------------------------------------------------------------------
__global__ __launch_bounds__(128) void attn_kernel(
    const int* __restrict__ mask, float* __restrict__ out)
{
    __shared__ float Ks[64][32];
    __shared__ float Vs[64][32];
    __shared__ float msk[64];

    const int tid = threadIdx.x;
    const int qt  = blockIdx.x;          // 0..3
    const int bmh = blockIdx.y;          // 0..1023
    const int h = bmh & (Hv - 1);
    const int m = (bmh >> 3) & (Mv - 1);
    const int b = bmh >> 7;

    const int t = qt * 128 + tid;
    const float scale = 0.17677669529663687f;   // 1/sqrt(32)

    const size_t qoff = ((size_t)(b * Tv + t) * Mv + m) * Pv + h * Ev;

    float qf[32];
    #pragma unroll
    for (int e = 0; e < 32; e++) qf[e] = g_q[qoff + e];

    float acc[32];
    #pragma unroll
    for (int e = 0; e < 32; e++) acc[e] = 0.f;
    float mval = -1e30f;
    float lsum = 0.f;

    for (int s0 = 0; s0 < Tv; s0 += 64) {
        #pragma unroll
        for (int i = tid; i < 64 * 8; i += 128) {
            int j  = i >> 3;
            int e4 = (i & 7) * 4;
            size_t koff = ((size_t)(b * Tv + s0 + j) * Mv + m) * Pv + h * Ev + e4;
            *(float4*)&Ks[j][e4] = *(const float4*)&g_k[koff];
            *(float4*)&Vs[j][e4] = *(const float4*)&g_v[koff];
        }
        if (tid < 64)
            msk[tid] = mask[((size_t)(b * Tv + s0 + tid)) * Mv + m] ? 1.f : 0.f;
        __syncthreads();

        #pragma unroll 2
        for (int j = 0; j < 64; j++) {
            if (msk[j] != 0.f) {       // uniform across the block -> no divergence
                float sc = 0.f;
                #pragma unroll
                for (int e = 0; e < 32; e++) sc += qf[e] * Ks[j][e];
                sc *= scale;
                if (sc > mval) {
                    float alpha = __expf(mval - sc);
                    mval = sc;
                    lsum *= alpha;
                    #pragma unroll
                    for (int e = 0; e < 32; e++) acc[e] *= alpha;
                }
                float p = __expf(sc - mval);
                lsum += p;
                #pragma unroll
                for (int e = 0; e < 32; e++) acc[e] += p * Vs[j][e];
            }
        }
        __syncthreads();
    }

    float inv = (lsum > 0.f) ? (1.0f / lsum) : 0.f;
    #pragma unroll
    for (int e = 0; e < 32; e += 4) {
        float4 o;
        o.x = acc[e + 0] * inv;
        o.y = acc[e + 1] * inv;
        o.z = acc[e + 2] * inv;
        o.w = acc[e + 3] * inv;
        *(float4*)&out[qoff + e] = o;
    }
}

// ---------------------------------------------------------------------------
// Inputs (metadata order): inp, mask, Wq, bq, Wk, bk, Wv, bv
// ---------------------------------------------------------------------------
extern "C" void kernel_launch(void* const* d_in, const int* in_sizes, int n_in,
                              void* d_out, int out_size)
{
    (void)in_sizes; (void)n_in; (void)out_size;
    const float* inp  = (const float*)d_in[0];
    const int*   mask = (const int*)d_in[1];
    const float* Wq = (const float*)d_in[2];
    const float* bq = (const float*)d_in[3];
    const float* Wk = (const float*)d_in[4];
    const float* bk = (const float*)d_in[5];
    const float* Wv = (const float*)d_in[6];
    const float* bv = (const float*)d_in[7];
    float* out = (float*)d_out;

    dim3 ggrid(ROWS / 64, Pv / 64);     // (1024, 4)
    qkv_gemm<<<ggrid, 256>>>(inp, Wq, bq, 0);
    qkv_gemm<<<ggrid, 256>>>(inp, Wk, bk, 1);
    qkv_gemm<<<ggrid, 256>>>(inp, Wv, bv, 2);

    dim3 agrid(Tv / 128, Bv * Mv * Hv); // (4, 1024)
    attn_kernel<<<agrid, 128>>>(mask, out);
}

// round 3
// speedup vs baseline: 1.0004x; 1.0004x over previous
#include <cuda_runtime.h>
#include <cuda_bf16.h>

#define Bv 8
#define Tv 512
#define Mv 16
#define Dv 128
#define Pv 256
#define Hv 8
#define Ev 32
#define ROWS (Bv*Tv*Mv)   // 65536

// Scratch for projected Q,K,V (layout identical to output: ((b*T+t)*M+m)*P + h*E + e)
__device__ float g_q[(size_t)ROWS * Pv];
__device__ float g_k[(size_t)ROWS * Pv];
__device__ float g_v[(size_t)ROWS * Pv];

// ---------------------------------------------------------------------------
// Fused QKV projection: one launch, blockIdx.z selects {Q,K,V}.
// C[r][c] = sum_k A[r][k] * W[k][c] + bias[c]
// A: [65536 x 128], W: [128 x 256]. 64x64 tile, BK=64, 256 thr, 4x4/thread.
// ---------------------------------------------------------------------------
__global__ __launch_bounds__(256) void qkv_gemm(
    const float* __restrict__ A,
    const float* __restrict__ Wq, const float* __restrict__ bq,
    const float* __restrict__ Wk, const float* __restrict__ bk,
    const float* __restrict__ Wv, const float* __restrict__ bv)
{
    __shared__ float As[64][65];
    __shared__ float Bs[64][64];

    const int which = blockIdx.z;
    const float* __restrict__ W    = (which == 0) ? Wq : (which == 1) ? Wk : Wv;
    const float* __restrict__ bias = (which == 0) ? bq : (which == 1) ? bk : bv;
    float* __restrict__ C          = (which == 0) ? g_q : (which == 1) ? g_k : g_v;

    const int tid = threadIdx.x;
    const int tx  = tid & 15;         // 0..15
    const int ty  = tid >> 4;         // 0..15
    const int rowBase = blockIdx.x * 64;
    const int colBase = blockIdx.y * 64;

    float acc[4][4] = {};

    for (int kk = 0; kk < Dv; kk += 64) {
        #pragma unroll
        for (int i = tid; i < 64 * 64; i += 256) {
            int r = i >> 6, k = i & 63;
            As[r][k] = A[(size_t)(rowBase + r) * Dv + kk + k];
        }
        #pragma unroll
        for (int i = tid; i < 64 * 64; i += 256) {
            int k = i >> 6, c = i & 63;
            Bs[k][c] = W[(size_t)(kk + k) * Pv + colBase + c];
        }
        __syncthreads();

        #pragma unroll 16
        for (int k = 0; k < 64; k++) {
            float a0 = As[ty * 4 + 0][k];
            float a1 = As[ty * 4 + 1][k];
            float a2 = As[ty * 4 + 2][k];
            float a3 = As[ty * 4 + 3][k];
            float4 bb = *(const float4*)&Bs[k][tx * 4];
            acc[0][0] += a0 * bb.x; acc[0][1] += a0 * bb.y; acc[0][2] += a0 * bb.z; acc[0][3] += a0 * bb.w;
            acc[1][0] += a1 * bb.x; acc[1][1] += a1 * bb.y; acc[1][2] += a1 * bb.z; acc[1][3] += a1 * bb.w;
            acc[2][0] += a2 * bb.x; acc[2][1] += a2 * bb.y; acc[2][2] += a2 * bb.z; acc[2][3] += a2 * bb.w;
            acc[3][0] += a3 * bb.x; acc[3][1] += a3 * bb.y; acc[3][2] += a3 * bb.z; acc[3][3] += a3 * bb.w;
        }
        __syncthreads();
    }

    #pragma unroll
    for (int i = 0; i < 4; i++) {
        int r = rowBase + ty * 4 + i;
        float4 o;
        o.x = acc[i][0] + bias[colBase + tx * 4 + 0];
        o.y = acc[i][1] + bias[colBase + tx * 4 + 1];
        o.z = acc[i][2] + bias[colBase + tx * 4 + 2];
        o.w = acc[i][3] + bias[colBase + tx * 4 + 3];
        *(float4*)&C[(size_t)r * Pv + colBase + tx * 4] = o;
    }
}

// ---------------------------------------------------------------------------
// Attention: one block per (q-tile of 128, bmh). 1 thread = 1 query row.
// K/V staged in smem 64 keys at a time as float4 so all shared reads are
// LDS.128 broadcasts (4x fewer L1 wavefronts than scalar).
// ---------------------------------------------------------------------------
__global__ __launch_bounds__(128) void attn_kernel(
    const int* __restrict__ mask, float* __restrict__ out)
{
    __shared__ float4 Ks[64][8];
    __shared__ float4 Vs[64][8];
    __shared__ float  msk[64];

    const int tid = threadIdx.x;
    const int qt  = blockIdx.x;          // 0..3
    const int bmh = blockIdx.y;          // 0..1023
    const int h = bmh & (Hv - 1);
    const int m = (bmh >> 3) & (Mv - 1);
    const int b = bmh >> 7;

    const int t = qt * 128 + tid;
    const float scale = 0.17677669529663687f;   // 1/sqrt(32)

    const size_t qoff = ((size_t)(b * Tv + t) * Mv + m) * Pv + h * Ev;

    float qf[32];
    #pragma unroll
    for (int e = 0; e < 32; e++) qf[e] = g_q[qoff + e];

    float acc[32];
    #pragma unroll
    for (int e = 0; e < 32; e++) acc[e] = 0.f;
    float mval = -1e30f;
    float lsum = 0.f;

    for (int s0 = 0; s0 < Tv; s0 += 64) {
        // Cooperative load of 64 K rows and 64 V rows (8 float4 = 128B each)
        #pragma unroll
        for (int i = tid; i < 64 * 8; i += 128) {
            int j  = i >> 3;
            int e4 = (i & 7);
            size_t koff = ((size_t)(b * Tv + s0 + j) * Mv + m) * Pv + h * Ev + e4 * 4;
            Ks[j][e4] = *(const float4*)&g_k[koff];
            Vs[j][e4] = *(const float4*)&g_v[koff];
        }
        if (tid < 64)
            msk[tid] = mask[((size_t)(b * Tv + s0 + tid)) * Mv + m] ? 1.f : 0.f;
        __syncthreads();

        #pragma unroll 2
        for (int j = 0; j < 64; j++) {
            if (msk[j] != 0.f) {       // uniform across block -> no divergence
                float sc = 0.f;
                #pragma unroll
                for (int e8 = 0; e8 < 8; e8++) {
                    float4 kk = Ks[j][e8];
                    sc += qf[e8 * 4 + 0] * kk.x;
                    sc += qf[e8 * 4 + 1] * kk.y;
                    sc += qf[e8 * 4 + 2] * kk.z;
                    sc += qf[e8 * 4 + 3] * kk.w;
                }
                sc *= scale;
                if (sc > mval) {       // rare after warmup
                    float alpha = __expf(mval - sc);
                    mval = sc;
                    lsum *= alpha;
                    #pragma unroll
                    for (int e = 0; e < 32; e++) acc[e] *= alpha;
                }
                float p = __expf(sc - mval);
                lsum += p;
                #pragma unroll
                for (int e8 = 0; e8 < 8; e8++) {
                    float4 vv = Vs[j][e8];
                    acc[e8 * 4 + 0] += p * vv.x;
                    acc[e8 * 4 + 1] += p * vv.y;
                    acc[e8 * 4 + 2] += p * vv.z;
                    acc[e8 * 4 + 3] += p * vv.w;
                }
            }
        }
        __syncthreads();
    }

    float inv = (lsum > 0.f) ? (1.0f / lsum) : 0.f;
    #pragma unroll
    for (int e = 0; e < 32; e += 4) {
        float4 o;
        o.x = acc[e + 0] * inv;
        o.y = acc[e + 1] * inv;
        o.z = acc[e + 2] * inv;
        o.w = acc[e + 3] * inv;
        *(float4*)&out[qoff + e] = o;
    }
}

// ---------------------------------------------------------------------------
// Inputs (metadata order): inp, mask, Wq, bq, Wk, bk, Wv, bv
// ---------------------------------------------------------------------------
extern "C" void kernel_launch(void* const* d_in, const int* in_sizes, int n_in,
                              void* d_out, int out_size)
{
    (void)in_sizes; (void)n_in; (void)out_size;
    const float* inp  = (const float*)d_in[0];
    const int*   mask = (const int*)d_in[1];
    const float* Wq = (const float*)d_in[2];
    const float* bq = (const float*)d_in[3];
    const float* Wk = (const float*)d_in[4];
    const float* bk = (const float*)d_in[5];
    const float* Wv = (const float*)d_in[6];
    const float* bv = (const float*)d_in[7];
    float* out = (float*)d_out;

    dim3 ggrid(ROWS / 64, Pv / 64, 3);  // (1024, 4, 3)
    qkv_gemm<<<ggrid, 256>>>(inp, Wq, bq, Wk, bk, Wv, bv);

    dim3 agrid(Tv / 128, Bv * Mv * Hv); // (4, 1024)
    attn_kernel<<<agrid, 128>>>(mask, out);
}

// round 4
// speedup vs baseline: 1.0361x; 1.0357x over previous
#include <cuda_runtime.h>
#include <cuda_bf16.h>

#define Bv 8
#define Tv 512
#define Mv 16
#define Dv 128
#define Pv 256
#define Hv 8
#define Ev 32
#define ROWS (Bv*Tv*Mv)   // 65536

// Scratch for projected Q,K,V (layout: ((b*T+t)*M+m)*P + h*E + e)
__device__ float g_q[(size_t)ROWS * Pv];
__device__ float g_k[(size_t)ROWS * Pv];
__device__ float g_v[(size_t)ROWS * Pv];

// ---------------------------------------------------------------------------
// Fused QKV projection: one launch, blockIdx.z selects {Q,K,V}.
// ---------------------------------------------------------------------------
__global__ __launch_bounds__(256) void qkv_gemm(
    const float* __restrict__ A,
    const float* __restrict__ Wq, const float* __restrict__ bq,
    const float* __restrict__ Wk, const float* __restrict__ bk,
    const float* __restrict__ Wv, const float* __restrict__ bv)
{
    __shared__ float As[64][65];
    __shared__ float Bs[64][64];

    const int which = blockIdx.z;
    const float* __restrict__ W    = (which == 0) ? Wq : (which == 1) ? Wk : Wv;
    const float* __restrict__ bias = (which == 0) ? bq : (which == 1) ? bk : bv;
    float* __restrict__ C          = (which == 0) ? g_q : (which == 1) ? g_k : g_v;

    const int tid = threadIdx.x;
    const int tx  = tid & 15;
    const int ty  = tid >> 4;
    const int rowBase = blockIdx.x * 64;
    const int colBase = blockIdx.y * 64;

    float acc[4][4] = {};

    for (int kk = 0; kk < Dv; kk += 64) {
        #pragma unroll
        for (int i = tid; i < 64 * 64; i += 256) {
            int r = i >> 6, k = i & 63;
            As[r][k] = A[(size_t)(rowBase + r) * Dv + kk + k];
        }
        #pragma unroll
        for (int i = tid; i < 64 * 64; i += 256) {
            int k = i >> 6, c = i & 63;
            Bs[k][c] = W[(size_t)(kk + k) * Pv + colBase + c];
        }
        __syncthreads();

        #pragma unroll 16
        for (int k = 0; k < 64; k++) {
            float a0 = As[ty * 4 + 0][k];
            float a1 = As[ty * 4 + 1][k];
            float a2 = As[ty * 4 + 2][k];
            float a3 = As[ty * 4 + 3][k];
            float4 bb = *(const float4*)&Bs[k][tx * 4];
            acc[0][0] += a0 * bb.x; acc[0][1] += a0 * bb.y; acc[0][2] += a0 * bb.z; acc[0][3] += a0 * bb.w;
            acc[1][0] += a1 * bb.x; acc[1][1] += a1 * bb.y; acc[1][2] += a1 * bb.z; acc[1][3] += a1 * bb.w;
            acc[2][0] += a2 * bb.x; acc[2][1] += a2 * bb.y; acc[2][2] += a2 * bb.z; acc[2][3] += a2 * bb.w;
            acc[3][0] += a3 * bb.x; acc[3][1] += a3 * bb.y; acc[3][2] += a3 * bb.z; acc[3][3] += a3 * bb.w;
        }
        __syncthreads();
    }

    #pragma unroll
    for (int i = 0; i < 4; i++) {
        int r = rowBase + ty * 4 + i;
        float4 o;
        o.x = acc[i][0] + bias[colBase + tx * 4 + 0];
        o.y = acc[i][1] + bias[colBase + tx * 4 + 1];
        o.z = acc[i][2] + bias[colBase + tx * 4 + 2];
        o.w = acc[i][3] + bias[colBase + tx * 4 + 3];
        *(float4*)&C[(size_t)r * Pv + colBase + tx * 4] = o;
    }
}

// ---------------------------------------------------------------------------
// Attention, register-blocked x2: each thread owns TWO query rows (t, t+128),
// so every K/V smem read is amortized over 128 FFMA instead of 64.
// Block covers 256 queries; grid = (Tv/256, B*M*H) = (2, 1024).
// ---------------------------------------------------------------------------
__global__ __launch_bounds__(128) void attn_kernel(
    const int* __restrict__ mask, float* __restrict__ out)
{
    __shared__ float4 Ks[64][8];
    __shared__ float4 Vs[64][8];
    __shared__ float  msk[64];

    const int tid = threadIdx.x;
    const int qt  = blockIdx.x;          // 0..1
    const int bmh = blockIdx.y;          // 0..1023
    const int h = bmh & (Hv - 1);
    const int m = (bmh >> 3) & (Mv - 1);
    const int b = bmh >> 7;

    const int t0 = qt * 256 + tid;
    const int t1 = t0 + 128;
    const float scale = 0.17677669529663687f;   // 1/sqrt(32)

    const size_t qoff0 = ((size_t)(b * Tv + t0) * Mv + m) * Pv + h * Ev;
    const size_t qoff1 = ((size_t)(b * Tv + t1) * Mv + m) * Pv + h * Ev;

    float qf0[32], qf1[32], acc0[32], acc1[32];
    #pragma unroll
    for (int e = 0; e < 32; e++) {
        qf0[e] = g_q[qoff0 + e];
        qf1[e] = g_q[qoff1 + e];
        acc0[e] = 0.f;
        acc1[e] = 0.f;
    }
    float m0 = -1e30f, m1 = -1e30f;
    float l0 = 0.f,    l1 = 0.f;

    for (int s0 = 0; s0 < Tv; s0 += 64) {
        #pragma unroll
        for (int i = tid; i < 64 * 8; i += 128) {
            int j  = i >> 3;
            int e4 = (i & 7);
            size_t koff = ((size_t)(b * Tv + s0 + j) * Mv + m) * Pv + h * Ev + e4 * 4;
            Ks[j][e4] = *(const float4*)&g_k[koff];
            Vs[j][e4] = *(const float4*)&g_v[koff];
        }
        if (tid < 64)
            msk[tid] = mask[((size_t)(b * Tv + s0 + tid)) * Mv + m] ? 1.f : 0.f;
        __syncthreads();

        for (int j = 0; j < 64; j++) {
            if (msk[j] != 0.f) {       // uniform across block -> no divergence
                float sc0 = 0.f, sc1 = 0.f;
                #pragma unroll
                for (int e8 = 0; e8 < 8; e8++) {
                    float4 kk = Ks[j][e8];
                    sc0 += qf0[e8 * 4 + 0] * kk.x;
                    sc0 += qf0[e8 * 4 + 1] * kk.y;
                    sc0 += qf0[e8 * 4 + 2] * kk.z;
                    sc0 += qf0[e8 * 4 + 3] * kk.w;
                    sc1 += qf1[e8 * 4 + 0] * kk.x;
                    sc1 += qf1[e8 * 4 + 1] * kk.y;
                    sc1 += qf1[e8 * 4 + 2] * kk.z;
                    sc1 += qf1[e8 * 4 + 3] * kk.w;
                }
                sc0 *= scale;
                sc1 *= scale;
                if (sc0 > m0) {        // rare after warmup
                    float alpha = __expf(m0 - sc0);
                    m0 = sc0;
                    l0 *= alpha;
                    #pragma unroll
                    for (int e = 0; e < 32; e++) acc0[e] *= alpha;
                }
                if (sc1 > m1) {
                    float alpha = __expf(m1 - sc1);
                    m1 = sc1;
                    l1 *= alpha;
                    #pragma unroll
                    for (int e = 0; e < 32; e++) acc1[e] *= alpha;
                }
                float p0 = __expf(sc0 - m0);
                float p1 = __expf(sc1 - m1);
                l0 += p0;
                l1 += p1;
                #pragma unroll
                for (int e8 = 0; e8 < 8; e8++) {
                    float4 vv = Vs[j][e8];
                    acc0[e8 * 4 + 0] += p0 * vv.x;
                    acc0[e8 * 4 + 1] += p0 * vv.y;
                    acc0[e8 * 4 + 2] += p0 * vv.z;
                    acc0[e8 * 4 + 3] += p0 * vv.w;
                    acc1[e8 * 4 + 0] += p1 * vv.x;
                    acc1[e8 * 4 + 1] += p1 * vv.y;
                    acc1[e8 * 4 + 2] += p1 * vv.z;
                    acc1[e8 * 4 + 3] += p1 * vv.w;
                }
            }
        }
        __syncthreads();
    }

    float inv0 = (l0 > 0.f) ? (1.0f / l0) : 0.f;
    float inv1 = (l1 > 0.f) ? (1.0f / l1) : 0.f;
    #pragma unroll
    for (int e = 0; e < 32; e += 4) {
        float4 o0, o1;
        o0.x = acc0[e + 0] * inv0; o0.y = acc0[e + 1] * inv0;
        o0.z = acc0[e + 2] * inv0; o0.w = acc0[e + 3] * inv0;
        o1.x = acc1[e + 0] * inv1; o1.y = acc1[e + 1] * inv1;
        o1.z = acc1[e + 2] * inv1; o1.w = acc1[e + 3] * inv1;
        *(float4*)&out[qoff0 + e] = o0;
        *(float4*)&out[qoff1 + e] = o1;
    }
}

// ---------------------------------------------------------------------------
// Inputs (metadata order): inp, mask, Wq, bq, Wk, bk, Wv, bv
// ---------------------------------------------------------------------------
extern "C" void kernel_launch(void* const* d_in, const int* in_sizes, int n_in,
                              void* d_out, int out_size)
{
    (void)in_sizes; (void)n_in; (void)out_size;
    const float* inp  = (const float*)d_in[0];
    const int*   mask = (const int*)d_in[1];
    const float* Wq = (const float*)d_in[2];
    const float* bq = (const float*)d_in[3];
    const float* Wk = (const float*)d_in[4];
    const float* bk = (const float*)d_in[5];
    const float* Wv = (const float*)d_in[6];
    const float* bv = (const float*)d_in[7];
    float* out = (float*)d_out;

    dim3 ggrid(ROWS / 64, Pv / 64, 3);  // (1024, 4, 3)
    qkv_gemm<<<ggrid, 256>>>(inp, Wq, bq, Wk, bk, Wv, bv);

    dim3 agrid(Tv / 256, Bv * Mv * Hv); // (2, 1024)
    attn_kernel<<<agrid, 128>>>(mask, out);
}